// round 11
// baseline (speedup 1.0000x reference)
#include <cuda_runtime.h>
#include <cuda_bf16.h>
#include <cstdint>

// DNGPU recurrence, round 10: A-resident split-bf16 HMMA GEMMs.
// R9 post-mortem: L1/LSU-bound -- A tile was re-streamed via cp.async every
// chunk (1024 of 1408 ops/chunk). Now A (66 halo rows x 192ch x 2 terms,
// 384B rows, mod-24 unit swizzle) is loaded ONCE into smem; the chunk loop
// streams only B. rg: M=64,N=96 (grid 256); cand: M=64,N=48 (grid 256);
// both 2 CTAs/SM. Same split products A0B0+A1B0+A0B1, identical numerics.

typedef __nv_bfloat16 bf16;
typedef __nv_bfloat162 bf162;

#define NB 32
#define NL 128
#define NC 192
#define PADL 130
#define KTOT 576
#define KCH 64
#define NCHUNK 27               // 1728 / 64
#define NPAIR 14
#define ATERM (66 * 384)        // one split-term A region: 25344 B
#define AREG (2 * ATERM)        // 50688 B

__device__ bf16 g_wt[3 * 2 * NC * KTOT];           // [conv][term][co][k*192+ci]
__device__ bf16 g_ma0[NB * PADL * NC], g_ma1[NB * PADL * NC];
__device__ bf16 g_mb0[NB * PADL * NC], g_mb1[NB * PADL * NC];
__device__ bf16 g_t0[NB * PADL * NC], g_t1[NB * PADL * NC];
__device__ float g_gate[NB * NL * NC];

#define CP16(d, s) \
    asm volatile("cp.async.cg.shared.global [%0], [%1], 16;" :: "r"(d), "l"(s))
#define CP_COMMIT() asm volatile("cp.async.commit_group;" ::: "memory")
#define CP_WAIT(n) asm volatile("cp.async.wait_group %0;" :: "n"(n) : "memory")

__device__ __forceinline__ uint32_t smem_u32(const void* p) {
    uint32_t a;
    asm("{ .reg .u64 t; cvta.to.shared.u64 t, %1; cvt.u32.u64 %0, t; }"
        : "=r"(a) : "l"(p));
    return a;
}
__device__ __forceinline__ void ldsm4(uint32_t (&r)[4], uint32_t a) {
    asm volatile("ldmatrix.sync.aligned.m8n8.x4.shared.b16 {%0,%1,%2,%3}, [%4];"
                 : "=r"(r[0]), "=r"(r[1]), "=r"(r[2]), "=r"(r[3]) : "r"(a));
}
__device__ __forceinline__ void ldsm2(uint32_t (&r)[2], uint32_t a) {
    asm volatile("ldmatrix.sync.aligned.m8n8.x2.shared.b16 {%0,%1}, [%2];"
                 : "=r"(r[0]), "=r"(r[1]) : "r"(a));
}
__device__ __forceinline__ void mma16816(float (&c)[4], const uint32_t (&a)[4],
                                         uint32_t b0, uint32_t b1) {
    asm volatile(
        "mma.sync.aligned.m16n8k16.row.col.f32.bf16.bf16.f32 "
        "{%0,%1,%2,%3}, {%4,%5,%6,%7}, {%8,%9}, {%0,%1,%2,%3};"
        : "+f"(c[0]), "+f"(c[1]), "+f"(c[2]), "+f"(c[3])
        : "r"(a[0]), "r"(a[1]), "r"(a[2]), "r"(a[3]), "r"(b0), "r"(b1));
}
__device__ __forceinline__ void split2(float v0, float v1, bf162& hp, bf162& lp) {
    bf16 h0 = __float2bfloat16(v0);
    bf16 h1 = __float2bfloat16(v1);
    hp.x = h0; hp.y = h1;
    lp.x = __float2bfloat16(v0 - __bfloat162float(h0));
    lp.y = __float2bfloat16(v1 - __bfloat162float(h1));
}

// M=64 GEMM, full K=1728 (3 products x 576). Smem: [B ring: 4 stages of
// BROWS*128][A: 2 terms x 66 rows x 384B, unit swizzle (u+3*(row&7))%24].
// NW = n8-tiles per warp-half: 6 (N=96) or 3 (N=48).
template <int NW>
__device__ __forceinline__ void gemm_run(char* smem,
                                         const bf16* __restrict__ a0,
                                         const bf16* __restrict__ a1,
                                         const bf16* __restrict__ b0,
                                         const bf16* __restrict__ b1,
                                         int tx, float (&acc)[NW][4]) {
    constexpr int BROWSL = NW * 16;
    constexpr int BST = BROWSL * 128;
    constexpr int ABASE = 4 * BST;
    const uint32_t sbase = smem_u32(smem);
    const uint32_t abase = sbase + ABASE;
    const int wid = tx >> 5, lane = tx & 31;
    const int mw = wid >> 1, nw = wid & 1;

    // ---- A preload: 66 rows x 24 units x 2 terms, once
    for (int t = tx; t < 3168; t += 256) {
        int term = t / 1584;
        int rem = t - term * 1584;
        int rr = rem / 24;
        int u = rem - rr * 24;
        uint32_t d = abase + term * ATERM + rr * 384 +
                     (((u + 3 * (rr & 7)) % 24) << 4);
        const bf16* s = (term ? a1 : a0) + rr * NC + u * 8;
        CP16(d, s);
    }
    CP_COMMIT();

    // ---- B cp.async offsets
    constexpr int BOPS = BROWSL * 8;          // 768 or 384
    constexpr int BJ = (BOPS + 255) / 256;    // 3 or 2
    uint32_t dB[BJ]; int sBo[BJ];
#pragma unroll
    for (int j = 0; j < BJ; j++) {
        int idx = tx + j * 256;
        int r = idx >> 3, u = idx & 7;
        dB[j] = r * 128 + ((u ^ (r & 7)) << 4);
        sBo[j] = r * KTOT + u * 8;
    }
    const bool vLast = (tx + (BJ - 1) * 256) < BOPS;

    // ---- A ldmatrix precompute (srow = tap + mrow)
    const int mrow = mw * 16 + ((lane >> 3) & 1) * 8 + (lane & 7);
    uint32_t preRB[3]; int preU[3][4];
#pragma unroll
    for (int k = 0; k < 3; k++) {
        int srow = k + mrow;
        preRB[k] = abase + srow * 384;
        int tw = 3 * (srow & 7);
#pragma unroll
        for (int h = 0; h < 4; h++)
            preU[k][h] = (2 * h + (lane >> 4) + tw) % 24;
    }

    // ---- B ldmatrix precompute
    uint32_t offB[NW == 6 ? 3 : 2][4];
    if constexpr (NW == 6) {
#pragma unroll
        for (int j2 = 0; j2 < 3; j2++) {
            int nrow = nw * 48 + j2 * 16 + ((lane >> 4) << 3) + (lane & 7);
#pragma unroll
            for (int h = 0; h < 4; h++)
                offB[j2][h] = nrow * 128 +
                              (((2 * h + ((lane >> 3) & 1)) ^ (nrow & 7)) << 4);
        }
    } else {
        int grp = lane >> 3;
        int j2s = grp >> 1, khs = grp & 1;
        int nrow = nw * 24 + j2s * 8 + (lane & 7);
#pragma unroll
        for (int h = 0; h < 4; h++)
            offB[0][h] = nrow * 128 + (((2 * h + khs) ^ (nrow & 7)) << 4);
        int nrow2 = nw * 24 + 16 + (lane & 7);
        int kh2 = (lane >> 3) & 1;
#pragma unroll
        for (int h = 0; h < 4; h++)
            offB[1][h] = nrow2 * 128 + (((2 * h + kh2) ^ (nrow2 & 7)) << 4);
    }

    auto issueB = [&](int q) {
        int p = q / 9, kc = q % 9;
        const bf16* bp = ((p == 2) ? b1 : b0) + kc * KCH;
        uint32_t st = sbase + (uint32_t)(q & 3) * BST;
#pragma unroll
        for (int j = 0; j < BJ - 1; j++) CP16(st + dB[j], bp + sBo[j]);
        if (vLast) CP16(st + dB[BJ - 1], bp + sBo[BJ - 1]);
        CP_COMMIT();
    };

    auto compute = [&](int q) {
        int p = q / 9, kc = q % 9;
        int k = kc / 3, u0 = (kc % 3) * 8;
        uint32_t at = (p == 1) ? (uint32_t)ATERM : 0u;
        uint32_t st = sbase + (uint32_t)(q & 3) * BST;
#pragma unroll
        for (int h = 0; h < 4; h++) {
            uint32_t af[4];
            int uu = preU[k][h] + u0;
            uu -= (uu >= 24) ? 24 : 0;
            ldsm4(af, preRB[k] + at + (uu << 4));
            if constexpr (NW == 6) {
                uint32_t bfm[3][4];
#pragma unroll
                for (int j2 = 0; j2 < 3; j2++) ldsm4(bfm[j2], st + offB[j2][h]);
#pragma unroll
                for (int jn = 0; jn < 6; jn++) {
                    int s = (jn & 1) * 2;
                    mma16816(acc[jn], af, bfm[jn >> 1][s], bfm[jn >> 1][s + 1]);
                }
            } else {
                uint32_t bq[4];
                ldsm4(bq, st + offB[0][h]);
                uint32_t b2[2];
                ldsm2(b2, st + offB[1][h]);
                mma16816(acc[0], af, bq[0], bq[1]);
                mma16816(acc[1], af, bq[2], bq[3]);
                mma16816(acc[2], af, b2[0], b2[1]);
            }
        }
    };

    issueB(0);
    issueB(1);

#pragma unroll 1
    for (int P = 0; P < NPAIR; P++) {
        const int q = 2 * P;
        CP_WAIT(0);                 // chunks q, q+1 (and A on first pair)
        __syncthreads();
        if (q + 2 < NCHUNK) issueB(q + 2);
        if (q + 3 < NCHUNK) issueB(q + 3);
        compute(q);
        if (q + 1 < NCHUNK) compute(q + 1);
    }
}

__device__ __forceinline__ float sigm(float x) { return 1.0f / (1.0f + expf(-x)); }

// ---------------- per-step kernels ----------------
__global__ void __launch_bounds__(256, 2)
rg_kernel(const bf16* __restrict__ cur0, const bf16* __restrict__ cur1,
          const float* __restrict__ br, const float* __restrict__ bg) {
    extern __shared__ char smem[];
    const int tx = threadIdx.x, bx = blockIdx.x;
    const int b = bx >> 3, conv = (bx >> 2) & 1, mh = (bx >> 1) & 1, nqh = bx & 1;
    const int r0 = mh * 64;
    const bf16* a0 = cur0 + ((size_t)b * PADL + r0) * NC;
    const bf16* a1 = cur1 + ((size_t)b * PADL + r0) * NC;
    const bf16* w0 = g_wt + ((size_t)(conv * 2 + 0) * NC + nqh * 96) * KTOT;
    const bf16* w1 = g_wt + ((size_t)(conv * 2 + 1) * NC + nqh * 96) * KTOT;

    float acc[6][4];
#pragma unroll
    for (int j = 0; j < 6; j++)
#pragma unroll
        for (int k = 0; k < 4; k++) acc[j][k] = 0.0f;

    gemm_run<6>(smem, a0, a1, w0, w1, tx, acc);

    const float* bias = conv ? bg : br;
    const int wid = tx >> 5, lane = tx & 31;
    const int mw = wid >> 1, nw = wid & 1;
    const int gr = lane >> 2, qc = (lane & 3) * 2;
#pragma unroll
    for (int jn = 0; jn < 6; jn++) {
        int ch = nqh * 96 + nw * 48 + jn * 8 + qc;
        float bv0 = bias[ch], bv1 = bias[ch + 1];
#pragma unroll
        for (int hf = 0; hf < 2; hf++) {
            int row = r0 + mw * 16 + gr + hf * 8;
            float s0 = sigm(acc[jn][hf * 2 + 0] + bv0);
            float s1 = sigm(acc[jn][hf * 2 + 1] + bv1);
            if (conv == 0) {
                size_t idx = ((size_t)b * PADL + row + 1) * NC + ch;
                bf162 h2 = *(const bf162*)(cur0 + idx);
                bf162 l2 = *(const bf162*)(cur1 + idx);
                float m0 = __bfloat162float(h2.x) + __bfloat162float(l2.x);
                float m1 = __bfloat162float(h2.y) + __bfloat162float(l2.y);
                bf162 hp, lp;
                split2(s0 * m0, s1 * m1, hp, lp);
                *(bf162*)(g_t0 + idx) = hp;
                *(bf162*)(g_t1 + idx) = lp;
            } else {
                float2 g2;
                g2.x = s0; g2.y = s1;
                *(float2*)(g_gate + ((size_t)b * NL + row) * NC + ch) = g2;
            }
        }
    }
}

__global__ void __launch_bounds__(256, 2)
cand_kernel(const bf16* __restrict__ cur0, const bf16* __restrict__ cur1,
            bf16* __restrict__ nxt0, bf16* __restrict__ nxt1,
            const float* __restrict__ bc, float* __restrict__ outp, int last) {
    extern __shared__ char smem[];
    const int tx = threadIdx.x, bx = blockIdx.x;
    const int b = bx >> 3, mh = (bx >> 2) & 1, nq = bx & 3;
    const int r0 = mh * 64;
    const bf16* a0 = g_t0 + ((size_t)b * PADL + r0) * NC;
    const bf16* a1 = g_t1 + ((size_t)b * PADL + r0) * NC;
    const bf16* w0 = g_wt + ((size_t)(2 * 2 + 0) * NC + nq * 48) * KTOT;
    const bf16* w1 = g_wt + ((size_t)(2 * 2 + 1) * NC + nq * 48) * KTOT;

    float acc[3][4];
#pragma unroll
    for (int j = 0; j < 3; j++)
#pragma unroll
        for (int k = 0; k < 4; k++) acc[j][k] = 0.0f;

    gemm_run<3>(smem, a0, a1, w0, w1, tx, acc);

    const int wid = tx >> 5, lane = tx & 31;
    const int mw = wid >> 1, nw = wid & 1;
    const int gr = lane >> 2, qc = (lane & 3) * 2;
#pragma unroll
    for (int jn = 0; jn < 3; jn++) {
        int ch = nq * 48 + nw * 24 + jn * 8 + qc;
        float bv0 = bc[ch], bv1 = bc[ch + 1];
#pragma unroll
        for (int hf = 0; hf < 2; hf++) {
            int row = r0 + mw * 16 + gr + hf * 8;
            float c0 = tanhf(acc[jn][hf * 2 + 0] + bv0);
            float c1 = tanhf(acc[jn][hf * 2 + 1] + bv1);
            float2 g2 = *(const float2*)(g_gate + ((size_t)b * NL + row) * NC + ch);
            size_t sidx = ((size_t)b * PADL + row) * NC + ch;   // mem[row-1]
            bf162 sh2 = *(const bf162*)(cur0 + sidx);
            bf162 sl2 = *(const bf162*)(cur1 + sidx);
            float sh0 = __bfloat162float(sh2.x) + __bfloat162float(sl2.x);
            float sh1 = __bfloat162float(sh2.y) + __bfloat162float(sl2.y);
            float o0 = g2.x * sh0 + (1.0f - g2.x) * c0;
            float o1 = g2.y * sh1 + (1.0f - g2.y) * c1;
            size_t didx = ((size_t)b * PADL + row + 1) * NC + ch;
            bf162 hp, lp;
            split2(o0, o1, hp, lp);
            *(bf162*)(nxt0 + didx) = hp;
            *(bf162*)(nxt1 + didx) = lp;
            if (last) {
                float2 o;
                o.x = o0; o.y = o1;
                *(float2*)(outp + ((size_t)b * NL + row) * NC + ch) = o;
            }
        }
    }
}

// ---------------- prep kernels ----------------
__global__ void zero_kernel() {
    int idx = blockIdx.x * 256 + threadIdx.x;
    const int n4 = NB * PADL * NC / 8;
    if (idx < n4) {
        uint4 z = make_uint4(0, 0, 0, 0);
        ((uint4*)g_ma0)[idx] = z;
        ((uint4*)g_ma1)[idx] = z;
        ((uint4*)g_mb0)[idx] = z;
        ((uint4*)g_mb1)[idx] = z;
        ((uint4*)g_t0)[idx] = z;
        ((uint4*)g_t1)[idx] = z;
    }
}

__global__ void aprep_kernel(const float* __restrict__ x) {
    int idx = blockIdx.x * 256 + threadIdx.x;
    if (idx >= NB * NL * NC) return;
    int ch = idx % NC;
    int l = (idx / NC) % NL;
    int b = idx / (NC * NL);
    float v = x[idx];
    bf16 h = __float2bfloat16(v);
    bf16 lo = __float2bfloat16(v - __bfloat162float(h));
    size_t d = ((size_t)b * PADL + l + 1) * NC + ch;
    g_ma0[d] = h;
    g_ma1[d] = lo;
}

__global__ void wprep_kernel(const float* __restrict__ wr,
                             const float* __restrict__ wg,
                             const float* __restrict__ wc) {
    int idx = blockIdx.x * 256 + threadIdx.x;
    if (idx >= 3 * 3 * NC * NC) return;
    int co = idx % NC;
    int t = idx / NC;
    int ci = t % NC; t /= NC;
    int k = t % 3, c = t / 3;
    const float* w = (c == 0) ? wr : (c == 1) ? wg : wc;
    float v = w[((size_t)k * NC + ci) * NC + co];
    bf16 h = __float2bfloat16(v);
    bf16 lo = __float2bfloat16(v - __bfloat162float(h));
    size_t base = (size_t)k * NC + ci;
    g_wt[((size_t)(c * 2 + 0) * NC + co) * KTOT + base] = h;
    g_wt[((size_t)(c * 2 + 1) * NC + co) * KTOT + base] = lo;
}

extern "C" void kernel_launch(void* const* d_in, const int* in_sizes, int n_in,
                              void* d_out, int out_size) {
    const float* x  = (const float*)d_in[0];
    const float* wr = (const float*)d_in[1];
    const float* br = (const float*)d_in[2];
    const float* wg = (const float*)d_in[3];
    const float* bg = (const float*)d_in[4];
    const float* wc = (const float*)d_in[5];
    const float* bc = (const float*)d_in[6];
    float* out = (float*)d_out;

    bf16 *ma0, *ma1, *mb0, *mb1;
    cudaGetSymbolAddress((void**)&ma0, g_ma0);
    cudaGetSymbolAddress((void**)&ma1, g_ma1);
    cudaGetSymbolAddress((void**)&mb0, g_mb0);
    cudaGetSymbolAddress((void**)&mb1, g_mb1);

    const int RG_SMEM = 4 * (96 * 128) + AREG;   // 49152 + 50688 = 99840
    const int CD_SMEM = 4 * (48 * 128) + AREG;   // 24576 + 50688 = 75264
    cudaFuncSetAttribute(rg_kernel, cudaFuncAttributeMaxDynamicSharedMemorySize,
                         RG_SMEM);
    cudaFuncSetAttribute(cand_kernel, cudaFuncAttributeMaxDynamicSharedMemorySize,
                         CD_SMEM);

    zero_kernel<<<(NB * PADL * NC / 8 + 255) / 256, 256>>>();
    wprep_kernel<<<(3 * 3 * NC * NC + 255) / 256, 256>>>(wr, wg, wc);
    aprep_kernel<<<(NB * NL * NC + 255) / 256, 256>>>(x);

    for (int s = 0; s < NL; s++) {
        bf16* c0 = (s & 1) ? mb0 : ma0;
        bf16* c1 = (s & 1) ? mb1 : ma1;
        bf16* n0 = (s & 1) ? ma0 : mb0;
        bf16* n1 = (s & 1) ? ma1 : mb1;
        rg_kernel<<<256, 256, RG_SMEM>>>(c0, c1, br, bg);
        cand_kernel<<<256, 256, CD_SMEM>>>(c0, c1, n0, n1, bc, out,
                                           s == NL - 1 ? 1 : 0);
    }
}

// round 12
// speedup vs baseline: 1.1518x; 1.1518x over previous
#include <cuda_runtime.h>
#include <cuda_bf16.h>
#include <cstdint>

// DNGPU recurrence, round 11: revert to R9 structure (best: 5785us) and fix
// its real limiter -- only 2 co-resident CTAs/SM meant every per-pair
// CP_WAIT+__syncthreads idled half the SM. rg now uses 128-thread CTAs
// (4 warps, same 32x24 warp tile as R9), tile M=64xN=48, grid 512, 4-stage
// 57KB ring -> 4 CTAs/SM, whole launch = one wave. cand kept as R9.
// Same split products A0B0+A1B0+A0B1, identical fragment code & numerics.

typedef __nv_bfloat16 bf16;
typedef __nv_bfloat162 bf162;

#define NB 32
#define NL 128
#define NC 192
#define PADL 130
#define KTOT 576
#define KCH 64
#define NCHUNK 27               // 1728 / 64
#define NPAIR 14
#define BROWS 48
#define BBYTES (BROWS * 128)    // 6144

__device__ bf16 g_wt[3 * 2 * NC * KTOT];           // [conv][term][co][k*192+ci]
__device__ bf16 g_ma0[NB * PADL * NC], g_ma1[NB * PADL * NC];
__device__ bf16 g_mb0[NB * PADL * NC], g_mb1[NB * PADL * NC];
__device__ bf16 g_t0[NB * PADL * NC], g_t1[NB * PADL * NC];
__device__ float g_gate[NB * NL * NC];

#define CP16(d, s) \
    asm volatile("cp.async.cg.shared.global [%0], [%1], 16;" :: "r"(d), "l"(s))
#define CP_COMMIT() asm volatile("cp.async.commit_group;" ::: "memory")
#define CP_WAIT(n) asm volatile("cp.async.wait_group %0;" :: "n"(n) : "memory")

__device__ __forceinline__ uint32_t smem_u32(const void* p) {
    uint32_t a;
    asm("{ .reg .u64 t; cvta.to.shared.u64 t, %1; cvt.u32.u64 %0, t; }"
        : "=r"(a) : "l"(p));
    return a;
}
__device__ __forceinline__ void ldsm4(uint32_t (&r)[4], uint32_t a) {
    asm volatile("ldmatrix.sync.aligned.m8n8.x4.shared.b16 {%0,%1,%2,%3}, [%4];"
                 : "=r"(r[0]), "=r"(r[1]), "=r"(r[2]), "=r"(r[3]) : "r"(a));
}
__device__ __forceinline__ void ldsm2(uint32_t (&r)[2], uint32_t a) {
    asm volatile("ldmatrix.sync.aligned.m8n8.x2.shared.b16 {%0,%1}, [%2];"
                 : "=r"(r[0]), "=r"(r[1]) : "r"(a));
}
__device__ __forceinline__ void mma16816(float (&c)[4], const uint32_t (&a)[4],
                                         uint32_t b0, uint32_t b1) {
    asm volatile(
        "mma.sync.aligned.m16n8k16.row.col.f32.bf16.bf16.f32 "
        "{%0,%1,%2,%3}, {%4,%5,%6,%7}, {%8,%9}, {%0,%1,%2,%3};"
        : "+f"(c[0]), "+f"(c[1]), "+f"(c[2]), "+f"(c[3])
        : "r"(a[0]), "r"(a[1]), "r"(a[2]), "r"(a[3]), "r"(b0), "r"(b1));
}
__device__ __forceinline__ void split2(float v0, float v1, bf162& hp, bf162& lp) {
    bf16 h0 = __float2bfloat16(v0);
    bf16 h1 = __float2bfloat16(v1);
    hp.x = h0; hp.y = h1;
    lp.x = __float2bfloat16(v0 - __bfloat162float(h0));
    lp.y = __float2bfloat16(v1 - __bfloat162float(h1));
}

// Full K=1728 (3 products x 576) GEMM. Stage layout: [A: M*128B][B: 6144B],
// 128B rows, 16B units, unit swizzle u ^= (row & 7).
// NT threads; warps: (NT/64) mw x 2 nw(24 cols, NW=3 n8-tiles).
template <int M, int MI, int NT>
__device__ __forceinline__ void gemm_run(char* ring,
                                         const bf16* __restrict__ a0,
                                         const bf16* __restrict__ a1,
                                         const bf16* __restrict__ b0,
                                         const bf16* __restrict__ b1,
                                         int tx, float (&acc)[MI][3][4]) {
    const uint32_t sbase = smem_u32(ring);
    constexpr int AB = M * 128;
    constexpr int STB = AB + BBYTES;    // one chunk stage
    constexpr int AOPS = M * 8;
    constexpr int AJ = AOPS / NT;       // exact for our configs
    constexpr int BOPS = BROWS * 8;     // 384
    constexpr int BJ = (BOPS + NT - 1) / NT;
    const int wid = tx >> 5, lane = tx & 31;
    const int mw = wid >> 1, nw = wid & 1;

    // ---- precomputed cp.async offsets
    uint32_t dA[AJ]; int sAo[AJ];
#pragma unroll
    for (int j = 0; j < AJ; j++) {
        int idx = tx + j * NT, r = idx >> 3, u = idx & 7;
        dA[j] = r * 128 + (((u ^ (r & 7))) << 4);
        sAo[j] = r * NC + u * 8;
    }
    uint32_t dB[BJ]; int sBo[BJ];
#pragma unroll
    for (int j = 0; j < BJ; j++) {
        int idx = tx + j * NT, r = (idx < BOPS ? idx : 0) >> 3, u = idx & 7;
        dB[j] = AB + r * 128 + (((u ^ (r & 7))) << 4);
        sBo[j] = r * KTOT + u * 8;
    }
    const bool vLast = (tx + (BJ - 1) * NT) < BOPS;

    // ---- precomputed ldmatrix fragment offsets
    uint32_t offA[MI][4], offB4[4], offB2[4];
#pragma unroll
    for (int im = 0; im < MI; im++) {
        int row = mw * (16 * MI) + im * 16 + ((lane >> 3) & 1) * 8 + (lane & 7);
#pragma unroll
        for (int h = 0; h < 4; h++)
            offA[im][h] = row * 128 + (((2 * h + (lane >> 4)) ^ (row & 7)) << 4);
    }
    {
        // x4: tiles (j2=0,k0),(j2=0,k1),(j2=1,k0),(j2=1,k1) via lane groups
        int grp = lane >> 3;            // 0..3
        int j2s = grp >> 1, khs = grp & 1;
        int nrow = nw * 24 + j2s * 8 + (lane & 7);
#pragma unroll
        for (int h = 0; h < 4; h++)
            offB4[h] = AB + nrow * 128 +
                       (((2 * h + khs) ^ (nrow & 7)) << 4);
        // x2: tile j2=2, two k-halves via lane groups 0,1
        int nrow2 = nw * 24 + 16 + (lane & 7);
        int kh2 = (lane >> 3) & 1;
#pragma unroll
        for (int h = 0; h < 4; h++)
            offB2[h] = AB + nrow2 * 128 +
                       (((2 * h + kh2) ^ (nrow2 & 7)) << 4);
    }

    // ---- chunk issue: q -> product p, tap, ci0; one commit group per chunk
    auto issue = [&](int q) {
        int p = q / 9, kc = q % 9;
        const bf16* ap = ((p == 1) ? a1 : a0) + (kc / 3) * NC + (kc % 3) * KCH;
        const bf16* bp = ((p == 2) ? b1 : b0) + kc * KCH;
        uint32_t st = sbase + (uint32_t)(q & 3) * STB;
#pragma unroll
        for (int j = 0; j < AJ; j++) CP16(st + dA[j], ap + sAo[j]);
#pragma unroll
        for (int j = 0; j < BJ - 1; j++) CP16(st + dB[j], bp + sBo[j]);
        if (vLast) CP16(st + dB[BJ - 1], bp + sBo[BJ - 1]);
        CP_COMMIT();
    };

    auto compute = [&](int q) {
        const uint32_t st = sbase + (uint32_t)(q & 3) * STB;
#pragma unroll
        for (int h = 0; h < 4; h++) {
            uint32_t af[MI][4];
#pragma unroll
            for (int im = 0; im < MI; im++) ldsm4(af[im], st + offA[im][h]);
            uint32_t bq[4];
            ldsm4(bq, st + offB4[h]);
            uint32_t b2[2];
            ldsm2(b2, st + offB2[h]);
#pragma unroll
            for (int im = 0; im < MI; im++) {
                mma16816(acc[im][0], af[im], bq[0], bq[1]);
                mma16816(acc[im][1], af[im], bq[2], bq[3]);
                mma16816(acc[im][2], af[im], b2[0], b2[1]);
            }
        }
    };

    issue(0);
    issue(1);

#pragma unroll 1
    for (int P = 0; P < NPAIR; P++) {
        const int q = 2 * P;
        CP_WAIT(0);                 // chunks q and q+1 landed
        __syncthreads();            // release of stages q+2,q+3
        if (q + 2 < NCHUNK) issue(q + 2);
        if (q + 3 < NCHUNK) issue(q + 3);
        compute(q);
        if (q + 1 < NCHUNK) compute(q + 1);
    }
}

__device__ __forceinline__ float sigm(float x) { return 1.0f / (1.0f + expf(-x)); }

// ---------------- per-step kernels ----------------
// rg: 128 threads, tile M=64 x N=48, grid 512, 4 CTAs/SM (one full wave).
__global__ void __launch_bounds__(128, 4)
rg_kernel(const bf16* __restrict__ cur0, const bf16* __restrict__ cur1,
          const float* __restrict__ br, const float* __restrict__ bg) {
    extern __shared__ char ring[];
    const int tx = threadIdx.x, bx = blockIdx.x;
    const int nq = bx & 3, mh = (bx >> 2) & 1, conv = (bx >> 3) & 1, b = bx >> 4;
    const int r0 = mh * 64;
    const bf16* a0 = cur0 + ((size_t)b * PADL + r0) * NC;
    const bf16* a1 = cur1 + ((size_t)b * PADL + r0) * NC;
    const bf16* w0 = g_wt + ((size_t)(conv * 2 + 0) * NC + nq * BROWS) * KTOT;
    const bf16* w1 = g_wt + ((size_t)(conv * 2 + 1) * NC + nq * BROWS) * KTOT;

    float acc[2][3][4];
#pragma unroll
    for (int i = 0; i < 2; i++)
#pragma unroll
        for (int j = 0; j < 3; j++)
#pragma unroll
            for (int k = 0; k < 4; k++) acc[i][j][k] = 0.0f;

    gemm_run<64, 2, 128>(ring, a0, a1, w0, w1, tx, acc);

    const float* bias = conv ? bg : br;
    const int wid = tx >> 5, lane = tx & 31;
    const int mw = wid >> 1, nw = wid & 1;
    const int gr = lane >> 2, qc = (lane & 3) * 2;
#pragma unroll
    for (int im = 0; im < 2; im++) {
#pragma unroll
        for (int jn = 0; jn < 3; jn++) {
            int ch = nq * BROWS + nw * 24 + jn * 8 + qc;
            float bv0 = bias[ch], bv1 = bias[ch + 1];
#pragma unroll
            for (int hf = 0; hf < 2; hf++) {
                int row = r0 + mw * 32 + im * 16 + gr + hf * 8;
                float s0 = sigm(acc[im][jn][hf * 2 + 0] + bv0);
                float s1 = sigm(acc[im][jn][hf * 2 + 1] + bv1);
                if (conv == 0) {
                    size_t idx = ((size_t)b * PADL + row + 1) * NC + ch;
                    bf162 h2 = *(const bf162*)(cur0 + idx);
                    bf162 l2 = *(const bf162*)(cur1 + idx);
                    float m0 = __bfloat162float(h2.x) + __bfloat162float(l2.x);
                    float m1 = __bfloat162float(h2.y) + __bfloat162float(l2.y);
                    bf162 hp, lp;
                    split2(s0 * m0, s1 * m1, hp, lp);
                    *(bf162*)(g_t0 + idx) = hp;
                    *(bf162*)(g_t1 + idx) = lp;
                } else {
                    float2 g2;
                    g2.x = s0; g2.y = s1;
                    *(float2*)(g_gate + ((size_t)b * NL + row) * NC + ch) = g2;
                }
            }
        }
    }
}

// cand: kept as R9 (256 threads, tile M=64 x N=48, grid 256, 2 CTAs/SM)
__global__ void __launch_bounds__(256, 2)
cand_kernel(const bf16* __restrict__ cur0, const bf16* __restrict__ cur1,
            bf16* __restrict__ nxt0, bf16* __restrict__ nxt1,
            const float* __restrict__ bc, float* __restrict__ outp, int last) {
    extern __shared__ char ring[];
    const int tx = threadIdx.x, bx = blockIdx.x;
    const int b = bx >> 3, mh = (bx >> 2) & 1, nq = bx & 3;
    const int r0 = mh * 64;
    const bf16* a0 = g_t0 + ((size_t)b * PADL + r0) * NC;
    const bf16* a1 = g_t1 + ((size_t)b * PADL + r0) * NC;
    const bf16* w0 = g_wt + ((size_t)(2 * 2 + 0) * NC + nq * BROWS) * KTOT;
    const bf16* w1 = g_wt + ((size_t)(2 * 2 + 1) * NC + nq * BROWS) * KTOT;

    float acc[1][3][4];
#pragma unroll
    for (int j = 0; j < 3; j++)
#pragma unroll
        for (int k = 0; k < 4; k++) acc[0][j][k] = 0.0f;

    gemm_run<64, 1, 256>(ring, a0, a1, w0, w1, tx, acc);

    const int wid = tx >> 5, lane = tx & 31;
    const int mw = wid >> 1, nw = wid & 1;
    const int gr = lane >> 2, qc = (lane & 3) * 2;
#pragma unroll
    for (int jn = 0; jn < 3; jn++) {
        int ch = nq * BROWS + nw * 24 + jn * 8 + qc;
        float bv0 = bc[ch], bv1 = bc[ch + 1];
#pragma unroll
        for (int hf = 0; hf < 2; hf++) {
            int row = r0 + mw * 16 + gr + hf * 8;
            float c0 = tanhf(acc[0][jn][hf * 2 + 0] + bv0);
            float c1 = tanhf(acc[0][jn][hf * 2 + 1] + bv1);
            float2 g2 = *(const float2*)(g_gate + ((size_t)b * NL + row) * NC + ch);
            size_t sidx = ((size_t)b * PADL + row) * NC + ch;   // mem[row-1]
            bf162 sh2 = *(const bf162*)(cur0 + sidx);
            bf162 sl2 = *(const bf162*)(cur1 + sidx);
            float sh0 = __bfloat162float(sh2.x) + __bfloat162float(sl2.x);
            float sh1 = __bfloat162float(sh2.y) + __bfloat162float(sl2.y);
            float o0 = g2.x * sh0 + (1.0f - g2.x) * c0;
            float o1 = g2.y * sh1 + (1.0f - g2.y) * c1;
            size_t didx = ((size_t)b * PADL + row + 1) * NC + ch;
            bf162 hp, lp;
            split2(o0, o1, hp, lp);
            *(bf162*)(nxt0 + didx) = hp;
            *(bf162*)(nxt1 + didx) = lp;
            if (last) {
                float2 o;
                o.x = o0; o.y = o1;
                *(float2*)(outp + ((size_t)b * NL + row) * NC + ch) = o;
            }
        }
    }
}

// ---------------- prep kernels ----------------
__global__ void zero_kernel() {
    int idx = blockIdx.x * 256 + threadIdx.x;
    const int n4 = NB * PADL * NC / 8;
    if (idx < n4) {
        uint4 z = make_uint4(0, 0, 0, 0);
        ((uint4*)g_ma0)[idx] = z;
        ((uint4*)g_ma1)[idx] = z;
        ((uint4*)g_mb0)[idx] = z;
        ((uint4*)g_mb1)[idx] = z;
        ((uint4*)g_t0)[idx] = z;
        ((uint4*)g_t1)[idx] = z;
    }
}

__global__ void aprep_kernel(const float* __restrict__ x) {
    int idx = blockIdx.x * 256 + threadIdx.x;
    if (idx >= NB * NL * NC) return;
    int ch = idx % NC;
    int l = (idx / NC) % NL;
    int b = idx / (NC * NL);
    float v = x[idx];
    bf16 h = __float2bfloat16(v);
    bf16 lo = __float2bfloat16(v - __bfloat162float(h));
    size_t d = ((size_t)b * PADL + l + 1) * NC + ch;
    g_ma0[d] = h;
    g_ma1[d] = lo;
}

__global__ void wprep_kernel(const float* __restrict__ wr,
                             const float* __restrict__ wg,
                             const float* __restrict__ wc) {
    int idx = blockIdx.x * 256 + threadIdx.x;
    if (idx >= 3 * 3 * NC * NC) return;
    int co = idx % NC;
    int t = idx / NC;
    int ci = t % NC; t /= NC;
    int k = t % 3, c = t / 3;
    const float* w = (c == 0) ? wr : (c == 1) ? wg : wc;
    float v = w[((size_t)k * NC + ci) * NC + co];
    bf16 h = __float2bfloat16(v);
    bf16 lo = __float2bfloat16(v - __bfloat162float(h));
    size_t base = (size_t)k * NC + ci;
    g_wt[((size_t)(c * 2 + 0) * NC + co) * KTOT + base] = h;
    g_wt[((size_t)(c * 2 + 1) * NC + co) * KTOT + base] = lo;
}

extern "C" void kernel_launch(void* const* d_in, const int* in_sizes, int n_in,
                              void* d_out, int out_size) {
    const float* x  = (const float*)d_in[0];
    const float* wr = (const float*)d_in[1];
    const float* br = (const float*)d_in[2];
    const float* wg = (const float*)d_in[3];
    const float* bg = (const float*)d_in[4];
    const float* wc = (const float*)d_in[5];
    const float* bc = (const float*)d_in[6];
    float* out = (float*)d_out;

    bf16 *ma0, *ma1, *mb0, *mb1;
    cudaGetSymbolAddress((void**)&ma0, g_ma0);
    cudaGetSymbolAddress((void**)&ma1, g_ma1);
    cudaGetSymbolAddress((void**)&mb0, g_mb0);
    cudaGetSymbolAddress((void**)&mb1, g_mb1);

    const int RG_SMEM = 4 * (64 * 128 + BBYTES);     // 57344
    const int CD_SMEM = 4 * (64 * 128 + BBYTES);     // 57344
    cudaFuncSetAttribute(rg_kernel, cudaFuncAttributeMaxDynamicSharedMemorySize,
                         RG_SMEM);
    cudaFuncSetAttribute(cand_kernel, cudaFuncAttributeMaxDynamicSharedMemorySize,
                         CD_SMEM);

    zero_kernel<<<(NB * PADL * NC / 8 + 255) / 256, 256>>>();
    wprep_kernel<<<(3 * 3 * NC * NC + 255) / 256, 256>>>(wr, wg, wc);
    aprep_kernel<<<(NB * NL * NC + 255) / 256, 256>>>(x);

    for (int s = 0; s < NL; s++) {
        bf16* c0 = (s & 1) ? mb0 : ma0;
        bf16* c1 = (s & 1) ? mb1 : ma1;
        bf16* n0 = (s & 1) ? ma0 : mb0;
        bf16* n1 = (s & 1) ? ma1 : mb1;
        rg_kernel<<<512, 128, RG_SMEM>>>(c0, c1, br, bg);
        cand_kernel<<<256, 256, CD_SMEM>>>(c0, c1, n0, n1, bc, out,
                                           s == NL - 1 ? 1 : 0);
    }
}

// round 13
// speedup vs baseline: 1.1557x; 1.0033x over previous
#include <cuda_runtime.h>
#include <cuda_bf16.h>
#include <cstdint>

// DNGPU recurrence, round 12: cut L1 wavefronts per MMA with bigger warp
// tiles. rg: 128-thread CTAs (2mw x 2nw), warp tile 32x48 (MI=2, NW=6 --
// R7's proven fragment path), CTA tile M=64 x N=96, grid 256; ldmatrix
// wf/MMA 2.33 -> 1.67 and A cp.async duplication 4x -> 2x (total L1 wf
// -29%). cand unchanged (R9 config). Same split products A0B0+A1B0+A0B1.

typedef __nv_bfloat16 bf16;
typedef __nv_bfloat162 bf162;

#define NB 32
#define NL 128
#define NC 192
#define PADL 130
#define KTOT 576
#define KCH 64
#define NCHUNK 27               // 1728 / 64
#define NPAIR 14

__device__ bf16 g_wt[3 * 2 * NC * KTOT];           // [conv][term][co][k*192+ci]
__device__ bf16 g_ma0[NB * PADL * NC], g_ma1[NB * PADL * NC];
__device__ bf16 g_mb0[NB * PADL * NC], g_mb1[NB * PADL * NC];
__device__ bf16 g_t0[NB * PADL * NC], g_t1[NB * PADL * NC];
__device__ float g_gate[NB * NL * NC];

#define CP16(d, s) \
    asm volatile("cp.async.cg.shared.global [%0], [%1], 16;" :: "r"(d), "l"(s))
#define CP_COMMIT() asm volatile("cp.async.commit_group;" ::: "memory")
#define CP_WAIT(n) asm volatile("cp.async.wait_group %0;" :: "n"(n) : "memory")

__device__ __forceinline__ uint32_t smem_u32(const void* p) {
    uint32_t a;
    asm("{ .reg .u64 t; cvta.to.shared.u64 t, %1; cvt.u32.u64 %0, t; }"
        : "=r"(a) : "l"(p));
    return a;
}
__device__ __forceinline__ void ldsm4(uint32_t (&r)[4], uint32_t a) {
    asm volatile("ldmatrix.sync.aligned.m8n8.x4.shared.b16 {%0,%1,%2,%3}, [%4];"
                 : "=r"(r[0]), "=r"(r[1]), "=r"(r[2]), "=r"(r[3]) : "r"(a));
}
__device__ __forceinline__ void ldsm2(uint32_t (&r)[2], uint32_t a) {
    asm volatile("ldmatrix.sync.aligned.m8n8.x2.shared.b16 {%0,%1}, [%2];"
                 : "=r"(r[0]), "=r"(r[1]) : "r"(a));
}
__device__ __forceinline__ void mma16816(float (&c)[4], const uint32_t (&a)[4],
                                         uint32_t b0, uint32_t b1) {
    asm volatile(
        "mma.sync.aligned.m16n8k16.row.col.f32.bf16.bf16.f32 "
        "{%0,%1,%2,%3}, {%4,%5,%6,%7}, {%8,%9}, {%0,%1,%2,%3};"
        : "+f"(c[0]), "+f"(c[1]), "+f"(c[2]), "+f"(c[3])
        : "r"(a[0]), "r"(a[1]), "r"(a[2]), "r"(a[3]), "r"(b0), "r"(b1));
}
__device__ __forceinline__ void split2(float v0, float v1, bf162& hp, bf162& lp) {
    bf16 h0 = __float2bfloat16(v0);
    bf16 h1 = __float2bfloat16(v1);
    hp.x = h0; hp.y = h1;
    lp.x = __float2bfloat16(v0 - __bfloat162float(h0));
    lp.y = __float2bfloat16(v1 - __bfloat162float(h1));
}

// Full K=1728 (3 products x 576) GEMM. Stage layout: [A: M*128B][B rows*128B],
// 128B rows, 16B units, unit swizzle u ^= (row & 7). Warps: (NT/64) mw x 2 nw.
// NW = n8-tiles per warp: 6 (48 cols) uses 3x ldsm4 B; 3 (24 cols) uses x4+x2.
template <int M, int MI, int NW, int NT>
__device__ __forceinline__ void gemm_run(char* ring,
                                         const bf16* __restrict__ a0,
                                         const bf16* __restrict__ a1,
                                         const bf16* __restrict__ b0,
                                         const bf16* __restrict__ b1,
                                         int tx, float (&acc)[MI][NW][4]) {
    const uint32_t sbase = smem_u32(ring);
    constexpr int BROWSL = (NW == 6) ? 96 : 48;
    constexpr int AB = M * 128;
    constexpr int STB = AB + BROWSL * 128;
    constexpr int AOPS = M * 8;
    constexpr int AJ = AOPS / NT;
    constexpr int BOPS = BROWSL * 8;
    constexpr int BJ = (BOPS + NT - 1) / NT;
    const int wid = tx >> 5, lane = tx & 31;
    const int mw = wid >> 1, nw = wid & 1;

    // ---- precomputed cp.async offsets
    uint32_t dA[AJ]; int sAo[AJ];
#pragma unroll
    for (int j = 0; j < AJ; j++) {
        int idx = tx + j * NT, r = idx >> 3, u = idx & 7;
        dA[j] = r * 128 + (((u ^ (r & 7))) << 4);
        sAo[j] = r * NC + u * 8;
    }
    uint32_t dB[BJ]; int sBo[BJ];
#pragma unroll
    for (int j = 0; j < BJ; j++) {
        int idx = tx + j * NT;
        int r = (idx < BOPS ? idx : 0) >> 3, u = idx & 7;
        dB[j] = AB + r * 128 + (((u ^ (r & 7))) << 4);
        sBo[j] = r * KTOT + u * 8;
    }
    const bool vLast = (tx + (BJ - 1) * NT) < BOPS;

    // ---- precomputed ldmatrix fragment offsets
    uint32_t offA[MI][4];
#pragma unroll
    for (int im = 0; im < MI; im++) {
        int row = mw * (16 * MI) + im * 16 + ((lane >> 3) & 1) * 8 + (lane & 7);
#pragma unroll
        for (int h = 0; h < 4; h++)
            offA[im][h] = row * 128 + (((2 * h + (lane >> 4)) ^ (row & 7)) << 4);
    }
    uint32_t offB[NW == 6 ? 3 : 2][4];
    if constexpr (NW == 6) {
#pragma unroll
        for (int j2 = 0; j2 < 3; j2++) {
            int nrow = nw * 48 + j2 * 16 + ((lane >> 4) << 3) + (lane & 7);
#pragma unroll
            for (int h = 0; h < 4; h++)
                offB[j2][h] = AB + nrow * 128 +
                              (((2 * h + ((lane >> 3) & 1)) ^ (nrow & 7)) << 4);
        }
    } else {
        int grp = lane >> 3;
        int j2s = grp >> 1, khs = grp & 1;
        int nrow = nw * 24 + j2s * 8 + (lane & 7);
#pragma unroll
        for (int h = 0; h < 4; h++)
            offB[0][h] = AB + nrow * 128 + (((2 * h + khs) ^ (nrow & 7)) << 4);
        int nrow2 = nw * 24 + 16 + (lane & 7);
        int kh2 = (lane >> 3) & 1;
#pragma unroll
        for (int h = 0; h < 4; h++)
            offB[1][h] = AB + nrow2 * 128 + (((2 * h + kh2) ^ (nrow2 & 7)) << 4);
    }

    // ---- chunk issue: q -> product p, tap, ci0; one commit group per chunk
    auto issue = [&](int q) {
        int p = q / 9, kc = q % 9;
        const bf16* ap = ((p == 1) ? a1 : a0) + (kc / 3) * NC + (kc % 3) * KCH;
        const bf16* bp = ((p == 2) ? b1 : b0) + kc * KCH;
        uint32_t st = sbase + (uint32_t)(q & 3) * STB;
#pragma unroll
        for (int j = 0; j < AJ; j++) CP16(st + dA[j], ap + sAo[j]);
#pragma unroll
        for (int j = 0; j < BJ - 1; j++) CP16(st + dB[j], bp + sBo[j]);
        if (vLast) CP16(st + dB[BJ - 1], bp + sBo[BJ - 1]);
        CP_COMMIT();
    };

    auto compute = [&](int q) {
        const uint32_t st = sbase + (uint32_t)(q & 3) * STB;
#pragma unroll
        for (int h = 0; h < 4; h++) {
            uint32_t af[MI][4];
#pragma unroll
            for (int im = 0; im < MI; im++) ldsm4(af[im], st + offA[im][h]);
            if constexpr (NW == 6) {
                uint32_t bfm[3][4];
#pragma unroll
                for (int j2 = 0; j2 < 3; j2++) ldsm4(bfm[j2], st + offB[j2][h]);
#pragma unroll
                for (int im = 0; im < MI; im++)
#pragma unroll
                    for (int jn = 0; jn < 6; jn++) {
                        int s = (jn & 1) * 2;
                        mma16816(acc[im][jn], af[im], bfm[jn >> 1][s],
                                 bfm[jn >> 1][s + 1]);
                    }
            } else {
                uint32_t bq[4];
                ldsm4(bq, st + offB[0][h]);
                uint32_t b2[2];
                ldsm2(b2, st + offB[1][h]);
#pragma unroll
                for (int im = 0; im < MI; im++) {
                    mma16816(acc[im][0], af[im], bq[0], bq[1]);
                    mma16816(acc[im][1], af[im], bq[2], bq[3]);
                    mma16816(acc[im][2], af[im], b2[0], b2[1]);
                }
            }
        }
    };

    issue(0);
    issue(1);

#pragma unroll 1
    for (int P = 0; P < NPAIR; P++) {
        const int q = 2 * P;
        CP_WAIT(0);                 // chunks q and q+1 landed
        __syncthreads();            // release of stages q+2,q+3
        if (q + 2 < NCHUNK) issue(q + 2);
        if (q + 3 < NCHUNK) issue(q + 3);
        compute(q);
        if (q + 1 < NCHUNK) compute(q + 1);
    }
}

__device__ __forceinline__ float sigm(float x) { return 1.0f / (1.0f + expf(-x)); }

// ---------------- per-step kernels ----------------
// rg: 128 threads (2mw x 2nw), tile M=64 x N=96, warp tile 32x48, grid 256.
__global__ void __launch_bounds__(128, 2)
rg_kernel(const bf16* __restrict__ cur0, const bf16* __restrict__ cur1,
          const float* __restrict__ br, const float* __restrict__ bg) {
    extern __shared__ char ring[];
    const int tx = threadIdx.x, bx = blockIdx.x;
    const int nqh = bx & 1, mh = (bx >> 1) & 1, conv = (bx >> 2) & 1, b = bx >> 3;
    const int r0 = mh * 64;
    const bf16* a0 = cur0 + ((size_t)b * PADL + r0) * NC;
    const bf16* a1 = cur1 + ((size_t)b * PADL + r0) * NC;
    const bf16* w0 = g_wt + ((size_t)(conv * 2 + 0) * NC + nqh * 96) * KTOT;
    const bf16* w1 = g_wt + ((size_t)(conv * 2 + 1) * NC + nqh * 96) * KTOT;

    float acc[2][6][4];
#pragma unroll
    for (int i = 0; i < 2; i++)
#pragma unroll
        for (int j = 0; j < 6; j++)
#pragma unroll
            for (int k = 0; k < 4; k++) acc[i][j][k] = 0.0f;

    gemm_run<64, 2, 6, 128>(ring, a0, a1, w0, w1, tx, acc);

    const float* bias = conv ? bg : br;
    const int wid = tx >> 5, lane = tx & 31;
    const int mw = wid >> 1, nw = wid & 1;
    const int gr = lane >> 2, qc = (lane & 3) * 2;
#pragma unroll
    for (int im = 0; im < 2; im++) {
#pragma unroll
        for (int jn = 0; jn < 6; jn++) {
            int ch = nqh * 96 + nw * 48 + jn * 8 + qc;
            float bv0 = bias[ch], bv1 = bias[ch + 1];
#pragma unroll
            for (int hf = 0; hf < 2; hf++) {
                int row = r0 + mw * 32 + im * 16 + gr + hf * 8;
                float s0 = sigm(acc[im][jn][hf * 2 + 0] + bv0);
                float s1 = sigm(acc[im][jn][hf * 2 + 1] + bv1);
                if (conv == 0) {
                    size_t idx = ((size_t)b * PADL + row + 1) * NC + ch;
                    bf162 h2 = *(const bf162*)(cur0 + idx);
                    bf162 l2 = *(const bf162*)(cur1 + idx);
                    float m0 = __bfloat162float(h2.x) + __bfloat162float(l2.x);
                    float m1 = __bfloat162float(h2.y) + __bfloat162float(l2.y);
                    bf162 hp, lp;
                    split2(s0 * m0, s1 * m1, hp, lp);
                    *(bf162*)(g_t0 + idx) = hp;
                    *(bf162*)(g_t1 + idx) = lp;
                } else {
                    float2 g2;
                    g2.x = s0; g2.y = s1;
                    *(float2*)(g_gate + ((size_t)b * NL + row) * NC + ch) = g2;
                }
            }
        }
    }
}

// cand: unchanged R9 config (256 threads, tile M=64 x N=48, grid 256).
__global__ void __launch_bounds__(256, 2)
cand_kernel(const bf16* __restrict__ cur0, const bf16* __restrict__ cur1,
            bf16* __restrict__ nxt0, bf16* __restrict__ nxt1,
            const float* __restrict__ bc, float* __restrict__ outp, int last) {
    extern __shared__ char ring[];
    const int tx = threadIdx.x, bx = blockIdx.x;
    const int b = bx >> 3, mh = (bx >> 2) & 1, nq = bx & 3;
    const int r0 = mh * 64;
    const bf16* a0 = g_t0 + ((size_t)b * PADL + r0) * NC;
    const bf16* a1 = g_t1 + ((size_t)b * PADL + r0) * NC;
    const bf16* w0 = g_wt + ((size_t)(2 * 2 + 0) * NC + nq * 48) * KTOT;
    const bf16* w1 = g_wt + ((size_t)(2 * 2 + 1) * NC + nq * 48) * KTOT;

    float acc[1][3][4];
#pragma unroll
    for (int j = 0; j < 3; j++)
#pragma unroll
        for (int k = 0; k < 4; k++) acc[0][j][k] = 0.0f;

    gemm_run<64, 1, 3, 256>(ring, a0, a1, w0, w1, tx, acc);

    const int wid = tx >> 5, lane = tx & 31;
    const int mw = wid >> 1, nw = wid & 1;
    const int gr = lane >> 2, qc = (lane & 3) * 2;
#pragma unroll
    for (int jn = 0; jn < 3; jn++) {
        int ch = nq * 48 + nw * 24 + jn * 8 + qc;
        float bv0 = bc[ch], bv1 = bc[ch + 1];
#pragma unroll
        for (int hf = 0; hf < 2; hf++) {
            int row = r0 + mw * 16 + gr + hf * 8;
            float c0 = tanhf(acc[0][jn][hf * 2 + 0] + bv0);
            float c1 = tanhf(acc[0][jn][hf * 2 + 1] + bv1);
            float2 g2 = *(const float2*)(g_gate + ((size_t)b * NL + row) * NC + ch);
            size_t sidx = ((size_t)b * PADL + row) * NC + ch;   // mem[row-1]
            bf162 sh2 = *(const bf162*)(cur0 + sidx);
            bf162 sl2 = *(const bf162*)(cur1 + sidx);
            float sh0 = __bfloat162float(sh2.x) + __bfloat162float(sl2.x);
            float sh1 = __bfloat162float(sh2.y) + __bfloat162float(sl2.y);
            float o0 = g2.x * sh0 + (1.0f - g2.x) * c0;
            float o1 = g2.y * sh1 + (1.0f - g2.y) * c1;
            size_t didx = ((size_t)b * PADL + row + 1) * NC + ch;
            bf162 hp, lp;
            split2(o0, o1, hp, lp);
            *(bf162*)(nxt0 + didx) = hp;
            *(bf162*)(nxt1 + didx) = lp;
            if (last) {
                float2 o;
                o.x = o0; o.y = o1;
                *(float2*)(outp + ((size_t)b * NL + row) * NC + ch) = o;
            }
        }
    }
}

// ---------------- prep kernels ----------------
__global__ void zero_kernel() {
    int idx = blockIdx.x * 256 + threadIdx.x;
    const int n4 = NB * PADL * NC / 8;
    if (idx < n4) {
        uint4 z = make_uint4(0, 0, 0, 0);
        ((uint4*)g_ma0)[idx] = z;
        ((uint4*)g_ma1)[idx] = z;
        ((uint4*)g_mb0)[idx] = z;
        ((uint4*)g_mb1)[idx] = z;
        ((uint4*)g_t0)[idx] = z;
        ((uint4*)g_t1)[idx] = z;
    }
}

__global__ void aprep_kernel(const float* __restrict__ x) {
    int idx = blockIdx.x * 256 + threadIdx.x;
    if (idx >= NB * NL * NC) return;
    int ch = idx % NC;
    int l = (idx / NC) % NL;
    int b = idx / (NC * NL);
    float v = x[idx];
    bf16 h = __float2bfloat16(v);
    bf16 lo = __float2bfloat16(v - __bfloat162float(h));
    size_t d = ((size_t)b * PADL + l + 1) * NC + ch;
    g_ma0[d] = h;
    g_ma1[d] = lo;
}

__global__ void wprep_kernel(const float* __restrict__ wr,
                             const float* __restrict__ wg,
                             const float* __restrict__ wc) {
    int idx = blockIdx.x * 256 + threadIdx.x;
    if (idx >= 3 * 3 * NC * NC) return;
    int co = idx % NC;
    int t = idx / NC;
    int ci = t % NC; t /= NC;
    int k = t % 3, c = t / 3;
    const float* w = (c == 0) ? wr : (c == 1) ? wg : wc;
    float v = w[((size_t)k * NC + ci) * NC + co];
    bf16 h = __float2bfloat16(v);
    bf16 lo = __float2bfloat16(v - __bfloat162float(h));
    size_t base = (size_t)k * NC + ci;
    g_wt[((size_t)(c * 2 + 0) * NC + co) * KTOT + base] = h;
    g_wt[((size_t)(c * 2 + 1) * NC + co) * KTOT + base] = lo;
}

extern "C" void kernel_launch(void* const* d_in, const int* in_sizes, int n_in,
                              void* d_out, int out_size) {
    const float* x  = (const float*)d_in[0];
    const float* wr = (const float*)d_in[1];
    const float* br = (const float*)d_in[2];
    const float* wg = (const float*)d_in[3];
    const float* bg = (const float*)d_in[4];
    const float* wc = (const float*)d_in[5];
    const float* bc = (const float*)d_in[6];
    float* out = (float*)d_out;

    bf16 *ma0, *ma1, *mb0, *mb1;
    cudaGetSymbolAddress((void**)&ma0, g_ma0);
    cudaGetSymbolAddress((void**)&ma1, g_ma1);
    cudaGetSymbolAddress((void**)&mb0, g_mb0);
    cudaGetSymbolAddress((void**)&mb1, g_mb1);

    const int RG_SMEM = 4 * (64 * 128 + 96 * 128);   // 81920
    const int CD_SMEM = 4 * (64 * 128 + 48 * 128);   // 57344
    cudaFuncSetAttribute(rg_kernel, cudaFuncAttributeMaxDynamicSharedMemorySize,
                         RG_SMEM);
    cudaFuncSetAttribute(cand_kernel, cudaFuncAttributeMaxDynamicSharedMemorySize,
                         CD_SMEM);

    zero_kernel<<<(NB * PADL * NC / 8 + 255) / 256, 256>>>();
    wprep_kernel<<<(3 * 3 * NC * NC + 255) / 256, 256>>>(wr, wg, wc);
    aprep_kernel<<<(NB * NL * NC + 255) / 256, 256>>>(x);

    for (int s = 0; s < NL; s++) {
        bf16* c0 = (s & 1) ? mb0 : ma0;
        bf16* c1 = (s & 1) ? mb1 : ma1;
        bf16* n0 = (s & 1) ? ma0 : mb0;
        bf16* n1 = (s & 1) ? ma1 : mb1;
        rg_kernel<<<256, 128, RG_SMEM>>>(c0, c1, br, bg);
        cand_kernel<<<256, 256, CD_SMEM>>>(c0, c1, n0, n1, bc, out,
                                           s == NL - 1 ? 1 : 0);
    }
}